// round 3
// baseline (speedup 1.0000x reference)
#include <cuda_runtime.h>
#include <math.h>

typedef unsigned long long ull;

// ---------------- packed f32x2 helpers (sm_103a) ----------------
__device__ __forceinline__ ull ffma2(ull a, ull b, ull c) {
    ull d;
    asm("fma.rn.f32x2 %0, %1, %2, %3;" : "=l"(d) : "l"(a), "l"(b), "l"(c));
    return d;
}
__device__ __forceinline__ ull dup2(float v) {
    ull r;
    asm("mov.b64 %0, {%1, %1};" : "=l"(r) : "f"(v));
    return r;
}
__device__ __forceinline__ float2 unp2(ull a) {
    float2 f;
    asm("mov.b64 {%0, %1}, %2;" : "=f"(f.x), "=f"(f.y) : "l"(a));
    return f;
}

// ---------------- scratch (allocation-free: __device__ globals) ----------------
#define MAXBUF (64*32*32*32)          // 2,097,152 floats
__device__ float g_wh  [64*32*8];     // reordered weights [ci][tap][co]
__device__ float g_wc0 [64*64*8];
__device__ float g_wr0 [64*64*27];
__device__ float g_wr1 [64*64*27];
__device__ float g_wc1 [64*64*27];
__device__ float g_wout[32*64*27];
__device__ float g_y [MAXBUF];
__device__ float g_t [MAXBUF];
__device__ float g_cA[MAXBUF];
__device__ float g_cB[64*16*16*16];
__device__ float g_part[4*1024*1024]; // split-K partial slabs (16 MB)

enum { M_PLAIN = 0, M_RELU = 1, M_ADD = 2, M_HALF = 3, M_GATE = 4 };

// reorder weights (O,I,taps) -> (I,taps,O)
__global__ void reorderw(const float* __restrict__ w, float* __restrict__ wT,
                         int cout, int cin, int taps) {
    int i = blockIdx.x * 256 + threadIdx.x;
    int n = cout * cin * taps;
    if (i >= n) return;
    int co = i / (cin * taps);
    int r  = i % (cin * taps);
    int ci = r / taps;
    int t  = r % taps;
    wT[((size_t)ci * taps + t) * cout + co] = w[i];
}

// ---------------- k3 s1 SAME conv, 2 voxels x 32 couts per thread ----------------
// grid.z = (d/4) * ngroups * nsplit ; blockDim = (tilex/2, 8, 4)
template<int MODE>
__global__ __launch_bounds__(256, 2)
void conv3p(const float* __restrict__ in, const float* __restrict__ wT,
            float* __restrict__ out, int d, int cinT, int coutT,
            int ngroups, int nsplit) {
    __shared__ float tf[6 * 10 * 18];
    __shared__ __align__(16) float ws[27 * 32];
    const int TXv = blockDim.x;          // 8 (tilex 16) or 4 (tilex 8)
    const int tilex = TXv * 2;
    const int hx_ = tilex + 2;
    const int tx = threadIdx.x, ty = threadIdx.y, tz = threadIdx.z;
    const int nth = TXv * 32;
    const int tid = (tz * 8 + ty) * TXv + tx;

    const int gs = ngroups * nsplit;
    const int zt = blockIdx.z / gs;
    const int rem = blockIdx.z % gs;
    const int g = rem / nsplit;
    const int s = rem % nsplit;
    const int x0 = blockIdx.x * tilex, y0 = blockIdx.y * 8, z0 = zt * 4;
    const int d2 = d * d, d3 = d2 * d;
    const int cin_per = cinT / nsplit;
    const int ci0 = s * cin_per;
    const int cb = g * 32;

    ull acc[2][16];
#pragma unroll
    for (int v = 0; v < 2; ++v)
#pragma unroll
        for (int p = 0; p < 16; ++p) acc[v][p] = 0ull;

    const int hn = 6 * 10 * hx_;
    for (int ci = ci0; ci < ci0 + cin_per; ++ci) {
        __syncthreads();
        const float* inc = in + (size_t)ci * d3;
        for (int i = tid; i < hn; i += nth) {
            int lx = i % hx_;
            int r2 = i / hx_;
            int ly = r2 % 10;
            int lz = r2 / 10;
            int gx = x0 + lx - 1, gy = y0 + ly - 1, gz = z0 + lz - 1;
            float v = 0.f;
            if ((unsigned)gx < (unsigned)d && (unsigned)gy < (unsigned)d &&
                (unsigned)gz < (unsigned)d)
                v = inc[(size_t)gz * d2 + gy * d + gx];
            tf[(lz * 10 + ly) * hx_ + lx] = v;
        }
        const float* wc = wT + (size_t)ci * 27 * coutT + cb;
        for (int i = tid; i < 27 * 32; i += nth) {
            int t = i >> 5, c = i & 31;
            ws[i] = wc[(size_t)t * coutT + c];
        }
        __syncthreads();

#pragma unroll
        for (int dz = 0; dz < 3; ++dz)
#pragma unroll
            for (int dy = 0; dy < 3; ++dy) {
                const float* row = tf + ((tz + dz) * 10 + ty + dy) * hx_ + 2 * tx;
                float rr[4];
                rr[0] = row[0]; rr[1] = row[1]; rr[2] = row[2]; rr[3] = row[3];
#pragma unroll
                for (int dx = 0; dx < 3; ++dx) {
                    ull v0 = dup2(rr[dx]);
                    ull v1 = dup2(rr[dx + 1]);
                    const ulonglong2* wp =
                        (const ulonglong2*)(ws + ((dz * 3 + dy) * 3 + dx) * 32);
#pragma unroll
                    for (int p = 0; p < 8; ++p) {
                        ulonglong2 w2 = wp[p];
                        acc[0][2 * p]     = ffma2(v0, w2.x, acc[0][2 * p]);
                        acc[0][2 * p + 1] = ffma2(v0, w2.y, acc[0][2 * p + 1]);
                        acc[1][2 * p]     = ffma2(v1, w2.x, acc[1][2 * p]);
                        acc[1][2 * p + 1] = ffma2(v1, w2.y, acc[1][2 * p + 1]);
                    }
                }
            }
    }

    const int gy = y0 + ty, gz = z0 + tz;
#pragma unroll
    for (int v = 0; v < 2; ++v) {
        const int gx = x0 + 2 * tx + v;
        const size_t idx = (size_t)gz * d2 + gy * d + gx;
#pragma unroll
        for (int p = 0; p < 16; ++p) {
            float2 f = unp2(acc[v][p]);
            float vals[2] = { f.x, f.y };
#pragma unroll
            for (int h = 0; h < 2; ++h) {
                int c = cb + 2 * p + h;
                float val = vals[h];
                if (nsplit > 1) {
                    out[((size_t)s * coutT + c) * d3 + idx] = val;
                } else {
                    if (MODE == M_RELU) val = fmaxf(val, 0.f);
                    if (MODE == M_HALF) val *= 0.5f;
                    float* o = out + (size_t)c * d3 + idx;
                    if (MODE == M_ADD) *o += val; else *o = val;
                }
            }
        }
    }
}

// ---------------- k2 s2 VALID conv (also gate when MODE==M_GATE) ----------------
template<int MODE>
__global__ __launch_bounds__(256, 2)
void conv2p(const float* __restrict__ in, const float* __restrict__ wT,
            float* __restrict__ out, int dout, int cinT, int coutT,
            int ngroups, int nsplit) {
    __shared__ __align__(16) float ws[8 * 32];
    const int TXv = blockDim.x;
    const int tilex = TXv * 2;
    const int tx = threadIdx.x, ty = threadIdx.y, tz = threadIdx.z;
    const int nth = TXv * 32;
    const int tid = (tz * 8 + ty) * TXv + tx;

    const int gs = ngroups * nsplit;
    const int zt = blockIdx.z / gs;
    const int rem = blockIdx.z % gs;
    const int g = rem / nsplit;
    const int s = rem % nsplit;
    const int gx0 = blockIdx.x * tilex + 2 * tx;   // out-x of voxel 0
    const int gy = blockIdx.y * 8 + ty, gz = zt * 4 + tz;
    const int din = dout * 2;
    const int din2 = din * din, din3 = din2 * din;
    const int do2 = dout * dout, do3 = do2 * dout;
    const int cin_per = cinT / nsplit, ci0 = s * cin_per;
    const int cb = g * 32;
    const size_t ibase = ((size_t)(2 * gz) * din + 2 * gy) * din + 2 * gx0;

    ull acc[2][16];
#pragma unroll
    for (int v = 0; v < 2; ++v)
#pragma unroll
        for (int p = 0; p < 16; ++p) acc[v][p] = 0ull;

    for (int ci = ci0; ci < ci0 + cin_per; ++ci) {
        __syncthreads();
        const float* wc = wT + (size_t)ci * 8 * coutT + cb;
        for (int i = tid; i < 8 * 32; i += nth) {
            int t = i >> 5, c = i & 31;
            ws[i] = wc[(size_t)t * coutT + c];
        }
        __syncthreads();
        const float* inc = in + (size_t)ci * din3;
        float4 q[4];
#pragma unroll
        for (int t = 0; t < 4; ++t) {
            int dz = t >> 1, dy = t & 1;
            q[t] = *(const float4*)(inc + ibase + (size_t)dz * din2 + dy * din);
        }
#pragma unroll
        for (int dz = 0; dz < 2; ++dz)
#pragma unroll
            for (int dy = 0; dy < 2; ++dy)
#pragma unroll
                for (int dx = 0; dx < 2; ++dx) {
                    const float4& qq = q[dz * 2 + dy];
                    float f0 = dx ? qq.y : qq.x;
                    float f1 = dx ? qq.w : qq.z;
                    ull v0 = dup2(f0), v1 = dup2(f1);
                    const ulonglong2* wp =
                        (const ulonglong2*)(ws + (dz * 4 + dy * 2 + dx) * 32);
#pragma unroll
                    for (int p = 0; p < 8; ++p) {
                        ulonglong2 w2 = wp[p];
                        acc[0][2 * p]     = ffma2(v0, w2.x, acc[0][2 * p]);
                        acc[0][2 * p + 1] = ffma2(v0, w2.y, acc[0][2 * p + 1]);
                        acc[1][2 * p]     = ffma2(v1, w2.x, acc[1][2 * p]);
                        acc[1][2 * p + 1] = ffma2(v1, w2.y, acc[1][2 * p + 1]);
                    }
                }
    }

#pragma unroll
    for (int v = 0; v < 2; ++v) {
        const int gx = gx0 + v;
        const size_t idx = (size_t)gz * do2 + gy * dout + gx;
#pragma unroll
        for (int p = 0; p < 16; ++p) {
            float2 f = unp2(acc[v][p]);
            float vals[2] = { f.x, f.y };
#pragma unroll
            for (int h = 0; h < 2; ++h) {
                int c = cb + 2 * p + h;
                float val = vals[h];
                if (nsplit > 1) {
                    out[((size_t)s * coutT + c) * do3 + idx] = val;
                } else if (MODE == M_GATE) {
                    float s2 = 2.f * val;   // undo hx 0.5 pre-scale
                    float gt = (s2 > 0.f) ? 1.f / (1.f + expf(-s2)) : 0.5f;
                    out[(size_t)c * do3 + idx] *= gt;
                } else {
                    if (MODE == M_RELU) val = fmaxf(val, 0.f);
                    if (MODE == M_HALF) val *= 0.5f;
                    float* o = out + (size_t)c * do3 + idx;
                    if (MODE == M_ADD) *o += val; else *o = val;
                }
            }
        }
    }
}

// ---------------- split-K reduction + activation ----------------
template<int MODE>
__global__ void reducek(const float* __restrict__ part, float* __restrict__ out,
                        int n, int stride, int nsplit) {
    int i = blockIdx.x * 256 + threadIdx.x;
    if (i >= n) return;
    float sum = 0.f;
    for (int s = 0; s < nsplit; ++s) sum += part[(size_t)s * stride + i];
    if (MODE == M_PLAIN) out[i] = sum;
    else if (MODE == M_RELU) out[i] = fmaxf(sum, 0.f);
    else if (MODE == M_ADD)  out[i] += sum;
    else if (MODE == M_HALF) out[i] = 0.5f * sum;
    else { // M_GATE: out is cx; sum is conv_h(hx*0.5)
        float s2 = 2.f * sum;
        float gt = (s2 > 0.f) ? 1.f / (1.f + expf(-s2)) : 0.5f;
        out[i] *= gt;
    }
}

// ---------------- host-side launch helpers ----------------
static void run3(const float* in, const float* w, float* out,
                 int d, int cin, int cout, int mode, int nsplit) {
    int tilex = (d >= 16) ? 16 : 8;
    dim3 B(tilex / 2, 8, 4);
    dim3 G(d / tilex, d / 8, (d / 4) * (cout / 32) * nsplit);
    if (nsplit > 1) mode = M_PLAIN;
    switch (mode) {
        case M_PLAIN: conv3p<M_PLAIN><<<G, B>>>(in, w, out, d, cin, cout, cout / 32, nsplit); break;
        case M_RELU:  conv3p<M_RELU ><<<G, B>>>(in, w, out, d, cin, cout, cout / 32, nsplit); break;
        case M_ADD:   conv3p<M_ADD  ><<<G, B>>>(in, w, out, d, cin, cout, cout / 32, nsplit); break;
        default:      conv3p<M_HALF ><<<G, B>>>(in, w, out, d, cin, cout, cout / 32, nsplit); break;
    }
}

static void run2(const float* in, const float* w, float* out,
                 int dout, int cin, int cout, int mode, int nsplit) {
    int tilex = (dout >= 16) ? 16 : 8;
    dim3 B(tilex / 2, 8, 4);
    dim3 G(dout / tilex, dout / 8, (dout / 4) * (cout / 32) * nsplit);
    if (nsplit > 1) mode = M_PLAIN;
    switch (mode) {
        case M_PLAIN: conv2p<M_PLAIN><<<G, B>>>(in, w, out, dout, cin, cout, cout / 32, nsplit); break;
        case M_RELU:  conv2p<M_RELU ><<<G, B>>>(in, w, out, dout, cin, cout, cout / 32, nsplit); break;
        case M_GATE:  conv2p<M_GATE ><<<G, B>>>(in, w, out, dout, cin, cout, cout / 32, nsplit); break;
        default:      conv2p<M_HALF ><<<G, B>>>(in, w, out, dout, cin, cout, cout / 32, nsplit); break;
    }
}

static void runred(const float* part, float* out, int n, int stride, int nsplit, int mode) {
    dim3 G((n + 255) / 256);
    switch (mode) {
        case M_PLAIN: reducek<M_PLAIN><<<G, 256>>>(part, out, n, stride, nsplit); break;
        case M_RELU:  reducek<M_RELU ><<<G, 256>>>(part, out, n, stride, nsplit); break;
        case M_ADD:   reducek<M_ADD  ><<<G, 256>>>(part, out, n, stride, nsplit); break;
        case M_HALF:  reducek<M_HALF ><<<G, 256>>>(part, out, n, stride, nsplit); break;
        default:      reducek<M_GATE ><<<G, 256>>>(part, out, n, stride, nsplit); break;
    }
}

// ---------------- driver ----------------
extern "C" void kernel_launch(void* const* d_in, const int* in_sizes, int n_in,
                              void* d_out, int out_size) {
    (void)in_sizes; (void)n_in; (void)out_size;
    const float* x     = (const float*)d_in[0];
    const float* w_h   = (const float*)d_in[1];
    const float* w_c0  = (const float*)d_in[2];
    const float* w_r0  = (const float*)d_in[3];
    const float* w_r1  = (const float*)d_in[4];
    const float* w_c1  = (const float*)d_in[5];
    const float* w_out = (const float*)d_in[6];
    float* out = (float*)d_out;

    float *wh, *wc0, *wr0, *wr1, *wc1, *wout, *bY, *bT, *bA, *bB, *bP;
    cudaGetSymbolAddress((void**)&wh,   g_wh);
    cudaGetSymbolAddress((void**)&wc0,  g_wc0);
    cudaGetSymbolAddress((void**)&wr0,  g_wr0);
    cudaGetSymbolAddress((void**)&wr1,  g_wr1);
    cudaGetSymbolAddress((void**)&wc1,  g_wc1);
    cudaGetSymbolAddress((void**)&wout, g_wout);
    cudaGetSymbolAddress((void**)&bY,   g_y);
    cudaGetSymbolAddress((void**)&bT,   g_t);
    cudaGetSymbolAddress((void**)&bA,   g_cA);
    cudaGetSymbolAddress((void**)&bB,   g_cB);
    cudaGetSymbolAddress((void**)&bP,   g_part);

    {
        int n;
        n = 64 * 32 * 8;  reorderw<<<(n + 255) / 256, 256>>>(w_h,   wh,   64, 32, 8);
        n = 64 * 64 * 8;  reorderw<<<(n + 255) / 256, 256>>>(w_c0,  wc0,  64, 64, 8);
        n = 64 * 64 * 27; reorderw<<<(n + 255) / 256, 256>>>(w_r0,  wr0,  64, 64, 27);
        n = 64 * 64 * 27; reorderw<<<(n + 255) / 256, 256>>>(w_r1,  wr1,  64, 64, 27);
        n = 64 * 64 * 27; reorderw<<<(n + 255) / 256, 256>>>(w_c1,  wc1,  64, 64, 27);
        n = 32 * 64 * 27; reorderw<<<(n + 255) / 256, 256>>>(w_out, wout, 32, 64, 27);
    }

    const size_t o0 = 0;
    const size_t o1 = o0 + (size_t)32 * 64 * 64 * 64;
    const size_t o2 = o1 + (size_t)32 * 32 * 32 * 32;
    const size_t o3 = o2 + (size_t)32 * 16 * 16 * 16;

    const int d3_32 = 32 * 32 * 32, d3_16 = 16 * 16 * 16, d3_8 = 8 * 8 * 8;

    // feas[0] = 0.5 * conv_out(x) @64 : 512 blocks, no split needed
    run3(x, wout, out + o0, 64, 64, 32, M_HALF, 1);

    // ---- iteration 1: d=32, nsplit=2 ----
    run2(x, wc0, bP, 32, 64, 64, M_PLAIN, 2);
    runred(bP, bY, 64 * d3_32, 64 * d3_32, 2, M_RELU);
    run3(bY, wr0, bP, 32, 64, 64, M_PLAIN, 2);
    runred(bP, bT, 64 * d3_32, 64 * d3_32, 2, M_RELU);
    run3(bT, wr1, bP, 32, 64, 64, M_PLAIN, 2);
    runred(bP, bY, 64 * d3_32, 64 * d3_32, 2, M_ADD);
    run3(bY, wc1, bP, 32, 64, 64, M_PLAIN, 2);
    runred(bP, bA, 64 * d3_32, 64 * d3_32, 2, M_PLAIN);
    run2(out + o0, wh, bP, 32, 32, 64, M_PLAIN, 2);
    runred(bP, bA, 64 * d3_32, 64 * d3_32, 2, M_GATE);
    run3(bA, wout, bP, 32, 64, 32, M_PLAIN, 2);
    runred(bP, out + o1, 32 * d3_32, 32 * d3_32, 2, M_HALF);

    // ---- iteration 2: d=16, nsplit=8 ----
    run2(bA, wc0, bP, 16, 64, 64, M_PLAIN, 8);
    runred(bP, bY, 64 * d3_16, 64 * d3_16, 8, M_RELU);
    run3(bY, wr0, bP, 16, 64, 64, M_PLAIN, 8);
    runred(bP, bT, 64 * d3_16, 64 * d3_16, 8, M_RELU);
    run3(bT, wr1, bP, 16, 64, 64, M_PLAIN, 8);
    runred(bP, bY, 64 * d3_16, 64 * d3_16, 8, M_ADD);
    run3(bY, wc1, bP, 16, 64, 64, M_PLAIN, 8);
    runred(bP, bB, 64 * d3_16, 64 * d3_16, 8, M_PLAIN);
    run2(out + o1, wh, bP, 16, 32, 64, M_PLAIN, 8);
    runred(bP, bB, 64 * d3_16, 64 * d3_16, 8, M_GATE);
    run3(bB, wout, bP, 16, 64, 32, M_PLAIN, 8);
    runred(bP, out + o2, 32 * d3_16, 32 * d3_16, 8, M_HALF);

    // ---- iteration 3: d=8, nsplit=16 ----
    run2(bB, wc0, bP, 8, 64, 64, M_PLAIN, 16);
    runred(bP, bY, 64 * d3_8, 64 * d3_8, 16, M_RELU);
    run3(bY, wr0, bP, 8, 64, 64, M_PLAIN, 16);
    runred(bP, bT, 64 * d3_8, 64 * d3_8, 16, M_RELU);
    run3(bT, wr1, bP, 8, 64, 64, M_PLAIN, 16);
    runred(bP, bY, 64 * d3_8, 64 * d3_8, 16, M_ADD);
    run3(bY, wc1, bP, 8, 64, 64, M_PLAIN, 16);
    runred(bP, bA, 64 * d3_8, 64 * d3_8, 16, M_PLAIN);
    run2(out + o2, wh, bP, 8, 32, 64, M_PLAIN, 16);
    runred(bP, bA, 64 * d3_8, 64 * d3_8, 16, M_GATE);
    run3(bA, wout, bP, 8, 64, 32, M_PLAIN, 16);
    runred(bP, out + o3, 32 * d3_8, 32 * d3_8, 16, M_HALF);
}

// round 5
// speedup vs baseline: 1.9434x; 1.9434x over previous
#include <cuda_runtime.h>
#include <cuda_fp16.h>
#include <math.h>

typedef unsigned int u32;
typedef unsigned long long u64;

enum { EP_RELU = 0, EP_PLAIN = 1, EP_ADD = 2, EP_GATE = 3, EP_OUT = 4, EP_PART = 5 };

// ---------------- device scratch (allocation-free) ----------------
__device__ float g_xv[64 * 64 * 64 * 64];   // x voxel-major [v][64]
__device__ float g_hv[64 * 64 * 64 * 32];   // hx voxel-major (scaled 0.5)
__device__ float g_y [32 * 32 * 32 * 64];
__device__ float g_t [32 * 32 * 32 * 64];
__device__ float g_cA[32 * 32 * 32 * 64];
__device__ float g_cB[16 * 16 * 16 * 64];
__device__ float g_part[4 * 1024 * 1024];
// packed weights: per (tap, chunk16) two blobs (hi, lo) of cout*16 halves in
// exact mma.sync B-fragment order
__device__ __half g_wh  [8  * 2 * 2 * 64 * 16];
__device__ __half g_wc0 [8  * 4 * 2 * 64 * 16];
__device__ __half g_wr0 [27 * 4 * 2 * 64 * 16];
__device__ __half g_wr1 [27 * 4 * 2 * 64 * 16];
__device__ __half g_wc1 [27 * 4 * 2 * 64 * 16];
__device__ __half g_wout[27 * 4 * 2 * 32 * 16];

// ---------------- helpers ----------------
__device__ __forceinline__ u32 s2u(const void* p) {
    u32 a;
    asm("{ .reg .u64 t; cvta.to.shared.u64 t, %1; cvt.u32.u64 %0, t; }" : "=r"(a) : "l"(p));
    return a;
}
__device__ __forceinline__ u32 p2(float a, float b) {
    __half2 h = __halves2half2(__float2half_rn(a), __float2half_rn(b));
    return *reinterpret_cast<u32*>(&h);
}
__device__ __forceinline__ float hrem(float a) {
    return a - __half2float(__float2half_rn(a));
}
__device__ __forceinline__ void ldm4(u32* r, u32 addr) {
    asm volatile("ldmatrix.sync.aligned.m8n8.x4.shared.b16 {%0,%1,%2,%3}, [%4];"
                 : "=r"(r[0]), "=r"(r[1]), "=r"(r[2]), "=r"(r[3]) : "r"(addr));
}
__device__ __forceinline__ void mma16816(float* c, const u32* a, uint2 b) {
    asm volatile(
        "mma.sync.aligned.m16n8k16.row.col.f32.f16.f16.f32 "
        "{%0,%1,%2,%3}, {%4,%5,%6,%7}, {%8,%9}, {%0,%1,%2,%3};"
        : "+f"(c[0]), "+f"(c[1]), "+f"(c[2]), "+f"(c[3])
        : "r"(a[0]), "r"(a[1]), "r"(a[2]), "r"(a[3]), "r"(b.x), "r"(b.y));
}
__device__ __forceinline__ float gatef(float a) {
    float s = 2.f * a;  // undo hx 0.5 pre-scale
    return (s > 0.f) ? 1.f / (1.f + expf(-s)) : 0.5f;
}

// ---------------- relayout x: NCDHW -> voxel-major [v][64] ----------------
__global__ void relayoutk(const float* __restrict__ in, float* __restrict__ outv, int d3) {
    __shared__ float s[64][33];
    int v0 = blockIdx.x * 32;
    int t = threadIdx.x;
    int vl = t & 31;
#pragma unroll
    for (int k = 0; k < 8; ++k) {
        int c = (t >> 5) + 8 * k;
        s[c][vl] = in[(size_t)c * d3 + v0 + vl];
    }
    __syncthreads();
    int vloc = t >> 3;
#pragma unroll
    for (int k = 0; k < 2; ++k) {
        int f4 = (t & 7) * 2 + k;
        float4 w = make_float4(s[f4 * 4 + 0][vloc], s[f4 * 4 + 1][vloc],
                               s[f4 * 4 + 2][vloc], s[f4 * 4 + 3][vloc]);
        *(float4*)(outv + (size_t)(v0 + vloc) * 64 + f4 * 4) = w;
    }
}

// ---------------- pack weights into B-fragment layout (hi/lo fp16) ----------------
// w layout (O,I,taps). Blob (t,q,pass): cout*16 halves; within blob, thread-lane
// fragment order for mma.sync m16n8k16 col-major B:
//   k = (l%4)*2 + h + 8r, n(within frag) = l/4
__global__ void packw(const float* __restrict__ w, __half* __restrict__ wp,
                      int cout, int cin, int taps) {
    int i = blockIdx.x * 256 + threadIdx.x;
    int n = cout * cin * taps;
    if (i >= n) return;
    int co = i / (cin * taps);
    int r = i % (cin * taps);
    int ci = r / taps;
    int t = r % taps;
    float v = w[i];
    float hi = __half2float(__float2half_rn(v));
    float lo = v - hi;
    int nch = cin >> 4;
    int q = ci >> 4, kk = ci & 15;
    int nf = co >> 3, nn = co & 7;
    int l = (nn << 2) + ((kk & 7) >> 1);
    int rr = kk >> 3, h = kk & 1;
    size_t base = (size_t)((t * nch + q) * 2) * (size_t)(cout * 16);
    size_t off = (size_t)nf * 128 + l * 4 + rr * 2 + h;
    wp[base + off] = __float2half_rn(hi);
    wp[base + cout * 16 + off] = __float2half_rn(lo);
}

// ---------------- tensor-core implicit conv (mma.sync, fp16 3-pass split) ----------------
// CTA: 128 thr = 4 warps; tile 8x4x4 = 128 voxels; warp w owns rows [32w,32w+32).
template<int KSZ, int N_, int MODE>
__global__ __launch_bounds__(128)
void convT(const float* __restrict__ in, const __half* __restrict__ wp,
           float* __restrict__ out0, float* __restrict__ out1,
           int d, int cin, int taps, int nsplit, int d3) {
    constexpr int NF = N_ / 8;
    __shared__ __align__(16) __half ah[(KSZ == 3) ? 5760 : 8];  // 360 rows x 16 halves
    __shared__ __align__(16) __half al[(KSZ == 3) ? 5760 : 8];

    const int tid = threadIdx.x, w = tid >> 5, lane = tid & 31;
    const int ntx = d >> 3, nty = d >> 2;
    int bt = blockIdx.x;
    const int x0 = (bt % ntx) << 3;
    bt /= ntx;
    const int y0 = (bt % nty) << 2;
    const int z0 = (bt / nty) << 2;
    const int sp = blockIdx.y;
    const int tpp = taps / nsplit;
    const int tap0 = sp * tpp;
    const int nch = cin >> 4;
    const int din = (KSZ == 2) ? 2 * d : d;

    float acc[2][NF][4];
#pragma unroll
    for (int mf = 0; mf < 2; ++mf)
#pragma unroll
        for (int nf = 0; nf < NF; ++nf)
#pragma unroll
            for (int k = 0; k < 4; ++k) acc[mf][nf][k] = 0.f;

    const u32 ahb = s2u(ah), alb = s2u(al);

    for (int q = 0; q < nch; ++q) {
        if (KSZ == 3) {
            __syncthreads();
            for (int i = tid; i < 1440; i += 128) {
                int row = i >> 2, c4 = i & 3;
                int hx = row % 10, r2 = row / 10, hy = r2 % 6, hz = r2 / 6;
                int gx = x0 + hx - 1, gy = y0 + hy - 1, gz = z0 + hz - 1;
                float4 v = make_float4(0.f, 0.f, 0.f, 0.f);
                if ((unsigned)gx < (unsigned)d && (unsigned)gy < (unsigned)d &&
                    (unsigned)gz < (unsigned)d)
                    v = *(const float4*)(in + ((size_t)(gz * d + gy) * d + gx) * cin
                                         + (q << 4) + (c4 << 2));
                uint2 hh, ll;
                hh.x = p2(v.x, v.y); hh.y = p2(v.z, v.w);
                ll.x = p2(hrem(v.x), hrem(v.y)); ll.y = p2(hrem(v.z), hrem(v.w));
                *(uint2*)(ah + row * 16 + c4 * 4) = hh;
                *(uint2*)(al + row * 16 + c4 * 4) = ll;
            }
            __syncthreads();
        }

        for (int tt = 0; tt < tpp; ++tt) {
            const int tap = tap0 + tt;
            int dzz, dyy, dxx;
            if (KSZ == 3) { dzz = tap / 9; dyy = (tap / 3) % 3; dxx = tap % 3; }
            else          { dzz = tap >> 2; dyy = (tap >> 1) & 1; dxx = tap & 1; }

            u32 AH[2][4], AL[2][4];
            if (KSZ == 3) {
#pragma unroll
                for (int mf = 0; mf < 2; ++mf) {
                    int r = lane & 15;
                    int mg = (w << 5) + (mf << 4) + r;
                    int lx = mg & 7, ly = (mg >> 3) & 3, lz = mg >> 5;
                    int rowi = ((lz + dzz) * 6 + ly + dyy) * 10 + lx + dxx;
                    u32 ao = (u32)rowi * 32 + ((lane >> 4) << 4);
                    ldm4(AH[mf], ahb + ao);
                    ldm4(AL[mf], alb + ao);
                }
            } else {
#pragma unroll
                for (int mf = 0; mf < 2; ++mf) {
                    int r = lane >> 2;
                    int cb = (q << 4) + ((lane & 3) << 1);
                    int mg0 = (w << 5) + (mf << 4) + r;
                    int mg1 = mg0 + 8;
                    int lx0 = mg0 & 7, ly0 = (mg0 >> 3) & 3, lz0 = mg0 >> 5;
                    int lx1 = mg1 & 7, ly1 = (mg1 >> 3) & 3, lz1 = mg1 >> 5;
                    size_t v0 = ((size_t)(2 * (z0 + lz0) + dzz) * din
                                 + (2 * (y0 + ly0) + dyy)) * din + 2 * (x0 + lx0) + dxx;
                    size_t v1 = ((size_t)(2 * (z0 + lz1) + dzz) * din
                                 + (2 * (y0 + ly1) + dyy)) * din + 2 * (x0 + lx1) + dxx;
                    float2 e00 = *(const float2*)(in + v0 * cin + cb);
                    float2 e10 = *(const float2*)(in + v1 * cin + cb);
                    float2 e01 = *(const float2*)(in + v0 * cin + cb + 8);
                    float2 e11 = *(const float2*)(in + v1 * cin + cb + 8);
                    AH[mf][0] = p2(e00.x, e00.y); AL[mf][0] = p2(hrem(e00.x), hrem(e00.y));
                    AH[mf][1] = p2(e10.x, e10.y); AL[mf][1] = p2(hrem(e10.x), hrem(e10.y));
                    AH[mf][2] = p2(e01.x, e01.y); AL[mf][2] = p2(hrem(e01.x), hrem(e01.y));
                    AH[mf][3] = p2(e11.x, e11.y); AL[mf][3] = p2(hrem(e11.x), hrem(e11.y));
                }
            }

            const __half* bb = wp + (size_t)((tap * nch + q) * 2) * (N_ * 16);
#pragma unroll
            for (int nf = 0; nf < NF; ++nf) {
                uint2 bh = *(const uint2*)(bb + nf * 128 + lane * 4);
                uint2 bl = *(const uint2*)(bb + N_ * 16 + nf * 128 + lane * 4);
                mma16816(acc[0][nf], AH[0], bh);
                mma16816(acc[1][nf], AH[1], bh);
                mma16816(acc[0][nf], AL[0], bh);
                mma16816(acc[1][nf], AL[1], bh);
                mma16816(acc[0][nf], AH[0], bl);
                mma16816(acc[1][nf], AH[1], bl);
            }
        }
    }

    // ---------------- epilogue ----------------
    const int rr = lane >> 2, cc = (lane & 3) << 1;
#pragma unroll
    for (int mf = 0; mf < 2; ++mf) {
        int mg0 = (w << 5) + (mf << 4) + rr;
        int mg1 = mg0 + 8;
        int lx0 = mg0 & 7, ly0 = (mg0 >> 3) & 3, lz0 = mg0 >> 5;
        int lx1 = mg1 & 7, ly1 = (mg1 >> 3) & 3, lz1 = mg1 >> 5;
        size_t v0 = ((size_t)(z0 + lz0) * d + (y0 + ly0)) * d + (x0 + lx0);
        size_t v1 = ((size_t)(z0 + lz1) * d + (y0 + ly1)) * d + (x0 + lx1);
#pragma unroll
        for (int nf = 0; nf < NF; ++nf) {
            int c0 = (nf << 3) + cc;
            float a0 = acc[mf][nf][0], a1 = acc[mf][nf][1];
            float a2 = acc[mf][nf][2], a3 = acc[mf][nf][3];
            if (MODE == EP_PART) {
                size_t slab = (size_t)sp * ((size_t)d * d * d * N_);
                *(float2*)(out0 + slab + v0 * N_ + c0) = make_float2(a0, a1);
                *(float2*)(out0 + slab + v1 * N_ + c0) = make_float2(a2, a3);
            } else if (MODE == EP_RELU || MODE == EP_PLAIN) {
                if (MODE == EP_RELU) {
                    a0 = fmaxf(a0, 0.f); a1 = fmaxf(a1, 0.f);
                    a2 = fmaxf(a2, 0.f); a3 = fmaxf(a3, 0.f);
                }
                *(float2*)(out0 + v0 * N_ + c0) = make_float2(a0, a1);
                *(float2*)(out0 + v1 * N_ + c0) = make_float2(a2, a3);
            } else if (MODE == EP_ADD) {
                float2 p0 = *(float2*)(out0 + v0 * N_ + c0);
                float2 p1 = *(float2*)(out0 + v1 * N_ + c0);
                p0.x += a0; p0.y += a1; p1.x += a2; p1.y += a3;
                *(float2*)(out0 + v0 * N_ + c0) = p0;
                *(float2*)(out0 + v1 * N_ + c0) = p1;
            } else if (MODE == EP_GATE) {
                float2 p0 = *(float2*)(out0 + v0 * N_ + c0);
                float2 p1 = *(float2*)(out0 + v1 * N_ + c0);
                p0.x *= gatef(a0); p0.y *= gatef(a1);
                p1.x *= gatef(a2); p1.y *= gatef(a3);
                *(float2*)(out0 + v0 * N_ + c0) = p0;
                *(float2*)(out0 + v1 * N_ + c0) = p1;
            } else {  // EP_OUT: channel-major 0.5x + voxel-major hx copy
                out0[(size_t)(c0 + 0) * d3 + v0] = 0.5f * a0;
                out0[(size_t)(c0 + 1) * d3 + v0] = 0.5f * a1;
                out0[(size_t)(c0 + 0) * d3 + v1] = 0.5f * a2;
                out0[(size_t)(c0 + 1) * d3 + v1] = 0.5f * a3;
                if (out1) {
                    *(float2*)(out1 + v0 * N_ + c0) = make_float2(0.5f * a0, 0.5f * a1);
                    *(float2*)(out1 + v1 * N_ + c0) = make_float2(0.5f * a2, 0.5f * a3);
                }
            }
        }
    }
}

// ---------------- split-K reduce (voxel-major) ----------------
template<int MODE>
__global__ void reduceT(const float* __restrict__ part, float* __restrict__ out0,
                        float* __restrict__ out1, int n, int slab, int nsplit,
                        int d3, int clog) {
    int i = blockIdx.x * 256 + threadIdx.x;
    if (i >= n) return;
    float s = 0.f;
    for (int k = 0; k < nsplit; ++k) s += part[(size_t)k * slab + i];
    if (MODE == EP_RELU) out0[i] = fmaxf(s, 0.f);
    else if (MODE == EP_PLAIN) out0[i] = s;
    else if (MODE == EP_ADD) out0[i] += s;
    else if (MODE == EP_GATE) out0[i] *= gatef(s);
    else {  // EP_OUT
        int c = i & ((1 << clog) - 1);
        int v = i >> clog;
        float h = 0.5f * s;
        out0[(size_t)c * d3 + v] = h;
        if (out1) out1[i] = h;
    }
}

// ---------------- driver ----------------
extern "C" void kernel_launch(void* const* d_in, const int* in_sizes, int n_in,
                              void* d_out, int out_size) {
    (void)in_sizes; (void)n_in; (void)out_size;
    const float* x     = (const float*)d_in[0];
    const float* w_h   = (const float*)d_in[1];
    const float* w_c0  = (const float*)d_in[2];
    const float* w_r0  = (const float*)d_in[3];
    const float* w_r1  = (const float*)d_in[4];
    const float* w_c1  = (const float*)d_in[5];
    const float* w_out = (const float*)d_in[6];
    float* out = (float*)d_out;

    float *xv, *hv, *bY, *bT, *cA, *cB, *bP;
    __half *wh, *wc0, *wr0, *wr1, *wc1, *wo;
    cudaGetSymbolAddress((void**)&xv, g_xv);
    cudaGetSymbolAddress((void**)&hv, g_hv);
    cudaGetSymbolAddress((void**)&bY, g_y);
    cudaGetSymbolAddress((void**)&bT, g_t);
    cudaGetSymbolAddress((void**)&cA, g_cA);
    cudaGetSymbolAddress((void**)&cB, g_cB);
    cudaGetSymbolAddress((void**)&bP, g_part);
    cudaGetSymbolAddress((void**)&wh, g_wh);
    cudaGetSymbolAddress((void**)&wc0, g_wc0);
    cudaGetSymbolAddress((void**)&wr0, g_wr0);
    cudaGetSymbolAddress((void**)&wr1, g_wr1);
    cudaGetSymbolAddress((void**)&wc1, g_wc1);
    cudaGetSymbolAddress((void**)&wo, g_wout);

    const int d3_64 = 262144, d3_32 = 32768, d3_16 = 4096, d3_8 = 512;

    relayoutk<<<d3_64 / 32, 256>>>(x, xv, d3_64);
    packw<<<(64 * 32 * 8 + 255) / 256, 256>>>(w_h, wh, 64, 32, 8);
    packw<<<(64 * 64 * 8 + 255) / 256, 256>>>(w_c0, wc0, 64, 64, 8);
    packw<<<(64 * 64 * 27 + 255) / 256, 256>>>(w_r0, wr0, 64, 64, 27);
    packw<<<(64 * 64 * 27 + 255) / 256, 256>>>(w_r1, wr1, 64, 64, 27);
    packw<<<(64 * 64 * 27 + 255) / 256, 256>>>(w_c1, wc1, 64, 64, 27);
    packw<<<(32 * 64 * 27 + 255) / 256, 256>>>(w_out, wo, 32, 64, 27);

    const size_t o0 = 0;
    const size_t o1 = o0 + (size_t)32 * d3_64;
    const size_t o2 = o1 + (size_t)32 * d3_32;
    const size_t o3 = o2 + (size_t)32 * d3_16;

    // feas[0] = 0.5*conv_out(x) @64 ; hv <- hx(scaled) voxel-major
    convT<3, 32, EP_OUT><<<2048, 128>>>(xv, wo, out + o0, hv, 64, 64, 27, 1, d3_64);

    // ---- iteration 1: d=32 (256 CTAs per conv) ----
    convT<2, 64, EP_RELU ><<<256, 128>>>(xv, wc0, bY, 0, 32, 64, 8, 1, 0);
    convT<3, 64, EP_RELU ><<<256, 128>>>(bY, wr0, bT, 0, 32, 64, 27, 1, 0);
    convT<3, 64, EP_ADD  ><<<256, 128>>>(bT, wr1, bY, 0, 32, 64, 27, 1, 0);
    convT<3, 64, EP_PLAIN><<<256, 128>>>(bY, wc1, cA, 0, 32, 64, 27, 1, 0);
    convT<2, 64, EP_GATE ><<<256, 128>>>(hv, wh, cA, 0, 32, 32, 8, 1, 0);
    convT<3, 32, EP_OUT  ><<<256, 128>>>(cA, wo, out + o1, hv, 32, 64, 27, 1, d3_32);

    // ---- iteration 2: d=16, tap-split ----
    {
        const int nv = d3_16, NB = nv / 128;
        convT<2, 64, EP_PART><<<dim3(NB, 4), 128>>>(cA, wc0, bP, 0, 16, 64, 8, 4, 0);
        reduceT<EP_RELU><<<(nv * 64 + 255) / 256, 256>>>(bP, bY, 0, nv * 64, nv * 64, 4, 0, 0);
        convT<3, 64, EP_PART><<<dim3(NB, 9), 128>>>(bY, wr0, bP, 0, 16, 64, 27, 9, 0);
        reduceT<EP_RELU><<<(nv * 64 + 255) / 256, 256>>>(bP, bT, 0, nv * 64, nv * 64, 9, 0, 0);
        convT<3, 64, EP_PART><<<dim3(NB, 9), 128>>>(bT, wr1, bP, 0, 16, 64, 27, 9, 0);
        reduceT<EP_ADD><<<(nv * 64 + 255) / 256, 256>>>(bP, bY, 0, nv * 64, nv * 64, 9, 0, 0);
        convT<3, 64, EP_PART><<<dim3(NB, 9), 128>>>(bY, wc1, bP, 0, 16, 64, 27, 9, 0);
        reduceT<EP_PLAIN><<<(nv * 64 + 255) / 256, 256>>>(bP, cB, 0, nv * 64, nv * 64, 9, 0, 0);
        convT<2, 64, EP_PART><<<dim3(NB, 4), 128>>>(hv, wh, bP, 0, 16, 32, 8, 4, 0);
        reduceT<EP_GATE><<<(nv * 64 + 255) / 256, 256>>>(bP, cB, 0, nv * 64, nv * 64, 4, 0, 0);
        convT<3, 32, EP_PART><<<dim3(NB, 9), 128>>>(cB, wo, bP, 0, 16, 64, 27, 9, 0);
        reduceT<EP_OUT><<<(nv * 32 + 255) / 256, 256>>>(bP, out + o2, hv, nv * 32, nv * 32, 9, d3_16, 5);
    }

    // ---- iteration 3: d=8, tap-split ----
    {
        const int nv = d3_8, NB = nv / 128;
        convT<2, 64, EP_PART><<<dim3(NB, 8), 128>>>(cB, wc0, bP, 0, 8, 64, 8, 8, 0);
        reduceT<EP_RELU><<<(nv * 64 + 255) / 256, 256>>>(bP, bY, 0, nv * 64, nv * 64, 8, 0, 0);
        convT<3, 64, EP_PART><<<dim3(NB, 27), 128>>>(bY, wr0, bP, 0, 8, 64, 27, 27, 0);
        reduceT<EP_RELU><<<(nv * 64 + 255) / 256, 256>>>(bP, bT, 0, nv * 64, nv * 64, 27, 0, 0);
        convT<3, 64, EP_PART><<<dim3(NB, 27), 128>>>(bT, wr1, bP, 0, 8, 64, 27, 27, 0);
        reduceT<EP_ADD><<<(nv * 64 + 255) / 256, 256>>>(bP, bY, 0, nv * 64, nv * 64, 27, 0, 0);
        convT<3, 64, EP_PART><<<dim3(NB, 27), 128>>>(bY, wc1, bP, 0, 8, 64, 27, 27, 0);
        reduceT<EP_PLAIN><<<(nv * 64 + 255) / 256, 256>>>(bP, cA, 0, nv * 64, nv * 64, 27, 0, 0);
        convT<2, 64, EP_PART><<<dim3(NB, 8), 128>>>(hv, wh, bP, 0, 8, 32, 8, 8, 0);
        reduceT<EP_GATE><<<(nv * 64 + 255) / 256, 256>>>(bP, cA, 0, nv * 64, nv * 64, 8, 0, 0);
        convT<3, 32, EP_PART><<<dim3(NB, 27), 128>>>(cA, wo, bP, 0, 8, 64, 27, 27, 0);
        reduceT<EP_OUT><<<(nv * 32 + 255) / 256, 256>>>(bP, out + o3, (float*)0, nv * 32, nv * 32, 27, d3_8, 5);
    }
}

// round 6
// speedup vs baseline: 2.1864x; 1.1250x over previous
#include <cuda_runtime.h>
#include <cuda_fp16.h>
#include <math.h>

typedef unsigned int u32;
typedef unsigned long long u64;

enum { EP_RELU = 0, EP_PLAIN = 1, EP_ADD = 2, EP_GATE = 3, EP_OUT = 4, EP_PART = 5 };

// ---------------- device scratch (allocation-free) ----------------
__device__ float g_xv[64 * 64 * 64 * 64];   // x voxel-major [v][64]
__device__ float g_hv[64 * 64 * 64 * 32];   // hx voxel-major (scaled 0.5)
__device__ float g_y [32 * 32 * 32 * 64];
__device__ float g_t [32 * 32 * 32 * 64];
__device__ float g_cA[32 * 32 * 32 * 64];
__device__ float g_cB[16 * 16 * 16 * 64];
__device__ float g_part[4 * 1024 * 1024];
// packed weights: per (tap, chunk16) two blobs (hi, lo) of cout*16 halves in
// exact mma.sync B-fragment order
__device__ __half g_wh  [8  * 2 * 2 * 64 * 16];
__device__ __half g_wc0 [8  * 4 * 2 * 64 * 16];
__device__ __half g_wr0 [27 * 4 * 2 * 64 * 16];
__device__ __half g_wr1 [27 * 4 * 2 * 64 * 16];
__device__ __half g_wc1 [27 * 4 * 2 * 64 * 16];
__device__ __half g_wout[27 * 4 * 2 * 32 * 16];

// ---------------- helpers ----------------
__device__ __forceinline__ u32 s2u(const void* p) {
    u32 a;
    asm("{ .reg .u64 t; cvta.to.shared.u64 t, %1; cvt.u32.u64 %0, t; }" : "=r"(a) : "l"(p));
    return a;
}
__device__ __forceinline__ u32 p2(float a, float b) {
    __half2 h = __halves2half2(__float2half_rn(a), __float2half_rn(b));
    return *reinterpret_cast<u32*>(&h);
}
__device__ __forceinline__ float hrem(float a) {
    return a - __half2float(__float2half_rn(a));
}
__device__ __forceinline__ void ldm4(u32* r, u32 addr) {
    asm volatile("ldmatrix.sync.aligned.m8n8.x4.shared.b16 {%0,%1,%2,%3}, [%4];"
                 : "=r"(r[0]), "=r"(r[1]), "=r"(r[2]), "=r"(r[3]) : "r"(addr));
}
__device__ __forceinline__ void mma16816(float* c, const u32* a, uint2 b) {
    asm volatile(
        "mma.sync.aligned.m16n8k16.row.col.f32.f16.f16.f32 "
        "{%0,%1,%2,%3}, {%4,%5,%6,%7}, {%8,%9}, {%0,%1,%2,%3};"
        : "+f"(c[0]), "+f"(c[1]), "+f"(c[2]), "+f"(c[3])
        : "r"(a[0]), "r"(a[1]), "r"(a[2]), "r"(a[3]), "r"(b.x), "r"(b.y));
}
__device__ __forceinline__ float gatef(float a) {
    float s = 2.f * a;  // undo hx 0.5 pre-scale
    return (s > 0.f) ? 1.f / (1.f + expf(-s)) : 0.5f;
}

// ---------------- relayout x: NCDHW -> voxel-major [v][64] ----------------
__global__ void relayoutk(const float* __restrict__ in, float* __restrict__ outv, int d3) {
    __shared__ float s[64][33];
    int v0 = blockIdx.x * 32;
    int t = threadIdx.x;
    int vl = t & 31;
#pragma unroll
    for (int k = 0; k < 8; ++k) {
        int c = (t >> 5) + 8 * k;
        s[c][vl] = in[(size_t)c * d3 + v0 + vl];
    }
    __syncthreads();
    int vloc = t >> 3;
#pragma unroll
    for (int k = 0; k < 2; ++k) {
        int f4 = (t & 7) * 2 + k;
        float4 w = make_float4(s[f4 * 4 + 0][vloc], s[f4 * 4 + 1][vloc],
                               s[f4 * 4 + 2][vloc], s[f4 * 4 + 3][vloc]);
        *(float4*)(outv + (size_t)(v0 + vloc) * 64 + f4 * 4) = w;
    }
}

// ---------------- pack ONE weight tensor region into B-fragment layout ----------------
__device__ __forceinline__ void packone(const float* __restrict__ w, __half* __restrict__ wp,
                                        int i, int cout, int cin, int taps) {
    int co = i / (cin * taps);
    int r = i % (cin * taps);
    int ci = r / taps;
    int t = r % taps;
    float v = w[i];
    float hi = __half2float(__float2half_rn(v));
    float lo = v - hi;
    int nch = cin >> 4;
    int q = ci >> 4, kk = ci & 15;
    int nf = co >> 3, nn = co & 7;
    int l = (nn << 2) + ((kk & 7) >> 1);
    int rr = kk >> 3, h = kk & 1;
    size_t base = (size_t)((t * nch + q) * 2) * (size_t)(cout * 16);
    size_t off = (size_t)nf * 128 + l * 4 + rr * 2 + h;
    wp[base + off] = __float2half_rn(hi);
    wp[base + cout * 16 + off] = __float2half_rn(lo);
}

// one launch packs all six weight tensors
__global__ void packall(const float* wh_, const float* wc0_, const float* wr0_,
                        const float* wr1_, const float* wc1_, const float* wout_,
                        __half* ph, __half* pc0, __half* pr0, __half* pr1,
                        __half* pc1, __half* pout) {
    int i = blockIdx.x * 256 + threadIdx.x;
    const int n0 = 64 * 32 * 8;            // w_h
    const int n1 = n0 + 64 * 64 * 8;       // w_c0
    const int n2 = n1 + 64 * 64 * 27;      // w_r0
    const int n3 = n2 + 64 * 64 * 27;      // w_r1
    const int n4 = n3 + 64 * 64 * 27;      // w_c1
    const int n5 = n4 + 32 * 64 * 27;      // w_out
    if (i < n0)      packone(wh_,  ph,  i,      64, 32, 8);
    else if (i < n1) packone(wc0_, pc0, i - n0, 64, 64, 8);
    else if (i < n2) packone(wr0_, pr0, i - n1, 64, 64, 27);
    else if (i < n3) packone(wr1_, pr1, i - n2, 64, 64, 27);
    else if (i < n4) packone(wc1_, pc1, i - n3, 64, 64, 27);
    else if (i < n5) packone(wout_, pout, i - n4, 32, 64, 27);
}

// ---------------- tensor-core implicit conv (mma.sync, fp16 3-pass split) ----------------
// CTA: 256 thr = 8 warps; tile 8x4x4 = 128 voxels.
// Warp w: m-rows [32*(w&3), +32), N-half (w>>2) -> nf in [half*NF/2, half*NF/2+NF/2)
template<int KSZ, int N_, int MODE>
__global__ __launch_bounds__(256, 3)
void convT(const float* __restrict__ in, const __half* __restrict__ wp,
           float* __restrict__ out0, float* __restrict__ out1,
           int d, int cin, int taps, int nsplit, int d3) {
    constexpr int NF = N_ / 8;
    constexpr int NFH = NF / 2;
    __shared__ __align__(16) __half ah[(KSZ == 3) ? 5760 : 8];  // 360 rows x 16 halves
    __shared__ __align__(16) __half al[(KSZ == 3) ? 5760 : 8];

    const int tid = threadIdx.x, w = tid >> 5, lane = tid & 31;
    const int wm = w & 3, half_ = w >> 2;
    const int ntx = d >> 3, nty = d >> 2;
    int bt = blockIdx.x;
    const int x0 = (bt % ntx) << 3;
    bt /= ntx;
    const int y0 = (bt % nty) << 2;
    const int z0 = (bt / nty) << 2;
    const int sp = blockIdx.y;
    const int tpp = taps / nsplit;
    const int tap0 = sp * tpp;
    const int nch = cin >> 4;
    const int din = (KSZ == 2) ? 2 * d : d;

    float acc[2][NFH][4];
#pragma unroll
    for (int mf = 0; mf < 2; ++mf)
#pragma unroll
        for (int nf = 0; nf < NFH; ++nf)
#pragma unroll
            for (int k = 0; k < 4; ++k) acc[mf][nf][k] = 0.f;

    const u32 ahb = s2u(ah), alb = s2u(al);

    for (int q = 0; q < nch; ++q) {
        if (KSZ == 3) {
            __syncthreads();
            for (int i = tid; i < 1440; i += 256) {
                int row = i >> 2, c4 = i & 3;
                int hx = row % 10, r2 = row / 10, hy = r2 % 6, hz = r2 / 6;
                int gx = x0 + hx - 1, gy = y0 + hy - 1, gz = z0 + hz - 1;
                float4 v = make_float4(0.f, 0.f, 0.f, 0.f);
                if ((unsigned)gx < (unsigned)d && (unsigned)gy < (unsigned)d &&
                    (unsigned)gz < (unsigned)d)
                    v = *(const float4*)(in + ((size_t)(gz * d + gy) * d + gx) * cin
                                         + (q << 4) + (c4 << 2));
                uint2 hh, ll;
                hh.x = p2(v.x, v.y); hh.y = p2(v.z, v.w);
                ll.x = p2(hrem(v.x), hrem(v.y)); ll.y = p2(hrem(v.z), hrem(v.w));
                *(uint2*)(ah + row * 16 + c4 * 4) = hh;
                *(uint2*)(al + row * 16 + c4 * 4) = ll;
            }
            __syncthreads();
        }

        for (int tt = 0; tt < tpp; ++tt) {
            const int tap = tap0 + tt;
            int dzz, dyy, dxx;
            if (KSZ == 3) { dzz = tap / 9; dyy = (tap / 3) % 3; dxx = tap % 3; }
            else          { dzz = tap >> 2; dyy = (tap >> 1) & 1; dxx = tap & 1; }

            u32 AH[2][4], AL[2][4];
            if (KSZ == 3) {
#pragma unroll
                for (int mf = 0; mf < 2; ++mf) {
                    int r = lane & 15;
                    int mg = (wm << 5) + (mf << 4) + r;
                    int lx = mg & 7, ly = (mg >> 3) & 3, lz = mg >> 5;
                    int rowi = ((lz + dzz) * 6 + ly + dyy) * 10 + lx + dxx;
                    u32 ao = (u32)rowi * 32 + ((lane >> 4) << 4);
                    ldm4(AH[mf], ahb + ao);
                    ldm4(AL[mf], alb + ao);
                }
            } else {
#pragma unroll
                for (int mf = 0; mf < 2; ++mf) {
                    int r = lane >> 2;
                    int cb = (q << 4) + ((lane & 3) << 1);
                    int mg0 = (wm << 5) + (mf << 4) + r;
                    int mg1 = mg0 + 8;
                    int lx0 = mg0 & 7, ly0 = (mg0 >> 3) & 3, lz0 = mg0 >> 5;
                    int lx1 = mg1 & 7, ly1 = (mg1 >> 3) & 3, lz1 = mg1 >> 5;
                    size_t v0 = ((size_t)(2 * (z0 + lz0) + dzz) * din
                                 + (2 * (y0 + ly0) + dyy)) * din + 2 * (x0 + lx0) + dxx;
                    size_t v1 = ((size_t)(2 * (z0 + lz1) + dzz) * din
                                 + (2 * (y0 + ly1) + dyy)) * din + 2 * (x0 + lx1) + dxx;
                    float2 e00 = *(const float2*)(in + v0 * cin + cb);
                    float2 e10 = *(const float2*)(in + v1 * cin + cb);
                    float2 e01 = *(const float2*)(in + v0 * cin + cb + 8);
                    float2 e11 = *(const float2*)(in + v1 * cin + cb + 8);
                    AH[mf][0] = p2(e00.x, e00.y); AL[mf][0] = p2(hrem(e00.x), hrem(e00.y));
                    AH[mf][1] = p2(e10.x, e10.y); AL[mf][1] = p2(hrem(e10.x), hrem(e10.y));
                    AH[mf][2] = p2(e01.x, e01.y); AL[mf][2] = p2(hrem(e01.x), hrem(e01.y));
                    AH[mf][3] = p2(e11.x, e11.y); AL[mf][3] = p2(hrem(e11.x), hrem(e11.y));
                }
            }

            const __half* bb = wp + (size_t)((tap * nch + q) * 2) * (N_ * 16);
#pragma unroll
            for (int nf = 0; nf < NFH; ++nf) {
                const int nfg = half_ * NFH + nf;
                uint2 bh = *(const uint2*)(bb + nfg * 128 + lane * 4);
                uint2 bl = *(const uint2*)(bb + N_ * 16 + nfg * 128 + lane * 4);
                mma16816(acc[0][nf], AH[0], bh);
                mma16816(acc[1][nf], AH[1], bh);
                mma16816(acc[0][nf], AL[0], bh);
                mma16816(acc[1][nf], AL[1], bh);
                mma16816(acc[0][nf], AH[0], bl);
                mma16816(acc[1][nf], AH[1], bl);
            }
        }
    }

    // ---------------- epilogue ----------------
    const int rr = lane >> 2, cc = (lane & 3) << 1;
#pragma unroll
    for (int mf = 0; mf < 2; ++mf) {
        int mg0 = (wm << 5) + (mf << 4) + rr;
        int mg1 = mg0 + 8;
        int lx0 = mg0 & 7, ly0 = (mg0 >> 3) & 3, lz0 = mg0 >> 5;
        int lx1 = mg1 & 7, ly1 = (mg1 >> 3) & 3, lz1 = mg1 >> 5;
        size_t v0 = ((size_t)(z0 + lz0) * d + (y0 + ly0)) * d + (x0 + lx0);
        size_t v1 = ((size_t)(z0 + lz1) * d + (y0 + ly1)) * d + (x0 + lx1);
#pragma unroll
        for (int nf = 0; nf < NFH; ++nf) {
            const int nfg = half_ * NFH + nf;
            int c0 = (nfg << 3) + cc;
            float a0 = acc[mf][nf][0], a1 = acc[mf][nf][1];
            float a2 = acc[mf][nf][2], a3 = acc[mf][nf][3];
            if (MODE == EP_PART) {
                size_t slab = (size_t)sp * ((size_t)d * d * d * N_);
                *(float2*)(out0 + slab + v0 * N_ + c0) = make_float2(a0, a1);
                *(float2*)(out0 + slab + v1 * N_ + c0) = make_float2(a2, a3);
            } else if (MODE == EP_RELU || MODE == EP_PLAIN) {
                if (MODE == EP_RELU) {
                    a0 = fmaxf(a0, 0.f); a1 = fmaxf(a1, 0.f);
                    a2 = fmaxf(a2, 0.f); a3 = fmaxf(a3, 0.f);
                }
                *(float2*)(out0 + v0 * N_ + c0) = make_float2(a0, a1);
                *(float2*)(out0 + v1 * N_ + c0) = make_float2(a2, a3);
            } else if (MODE == EP_ADD) {
                float2 p0 = *(float2*)(out0 + v0 * N_ + c0);
                float2 p1 = *(float2*)(out0 + v1 * N_ + c0);
                p0.x += a0; p0.y += a1; p1.x += a2; p1.y += a3;
                *(float2*)(out0 + v0 * N_ + c0) = p0;
                *(float2*)(out0 + v1 * N_ + c0) = p1;
            } else if (MODE == EP_GATE) {
                float2 p0 = *(float2*)(out0 + v0 * N_ + c0);
                float2 p1 = *(float2*)(out0 + v1 * N_ + c0);
                p0.x *= gatef(a0); p0.y *= gatef(a1);
                p1.x *= gatef(a2); p1.y *= gatef(a3);
                *(float2*)(out0 + v0 * N_ + c0) = p0;
                *(float2*)(out0 + v1 * N_ + c0) = p1;
            } else {  // EP_OUT: channel-major 0.5x + voxel-major hx copy
                out0[(size_t)(c0 + 0) * d3 + v0] = 0.5f * a0;
                out0[(size_t)(c0 + 1) * d3 + v0] = 0.5f * a1;
                out0[(size_t)(c0 + 0) * d3 + v1] = 0.5f * a2;
                out0[(size_t)(c0 + 1) * d3 + v1] = 0.5f * a3;
                if (out1) {
                    *(float2*)(out1 + v0 * N_ + c0) = make_float2(0.5f * a0, 0.5f * a1);
                    *(float2*)(out1 + v1 * N_ + c0) = make_float2(0.5f * a2, 0.5f * a3);
                }
            }
        }
    }
}

// ---------------- split-K reduce (voxel-major) ----------------
template<int MODE>
__global__ void reduceT(const float* __restrict__ part, float* __restrict__ out0,
                        float* __restrict__ out1, int n, int slab, int nsplit,
                        int d3, int clog) {
    int i = blockIdx.x * 256 + threadIdx.x;
    if (i >= n) return;
    float s = 0.f;
    for (int k = 0; k < nsplit; ++k) s += part[(size_t)k * slab + i];
    if (MODE == EP_RELU) out0[i] = fmaxf(s, 0.f);
    else if (MODE == EP_PLAIN) out0[i] = s;
    else if (MODE == EP_ADD) out0[i] += s;
    else if (MODE == EP_GATE) out0[i] *= gatef(s);
    else {  // EP_OUT
        int c = i & ((1 << clog) - 1);
        int v = i >> clog;
        float h = 0.5f * s;
        out0[(size_t)c * d3 + v] = h;
        if (out1) out1[i] = h;
    }
}

// ---------------- driver ----------------
extern "C" void kernel_launch(void* const* d_in, const int* in_sizes, int n_in,
                              void* d_out, int out_size) {
    (void)in_sizes; (void)n_in; (void)out_size;
    const float* x     = (const float*)d_in[0];
    const float* w_h   = (const float*)d_in[1];
    const float* w_c0  = (const float*)d_in[2];
    const float* w_r0  = (const float*)d_in[3];
    const float* w_r1  = (const float*)d_in[4];
    const float* w_c1  = (const float*)d_in[5];
    const float* w_out = (const float*)d_in[6];
    float* out = (float*)d_out;

    float *xv, *hv, *bY, *bT, *cA, *cB, *bP;
    __half *wh, *wc0, *wr0, *wr1, *wc1, *wo;
    cudaGetSymbolAddress((void**)&xv, g_xv);
    cudaGetSymbolAddress((void**)&hv, g_hv);
    cudaGetSymbolAddress((void**)&bY, g_y);
    cudaGetSymbolAddress((void**)&bT, g_t);
    cudaGetSymbolAddress((void**)&cA, g_cA);
    cudaGetSymbolAddress((void**)&cB, g_cB);
    cudaGetSymbolAddress((void**)&bP, g_part);
    cudaGetSymbolAddress((void**)&wh, g_wh);
    cudaGetSymbolAddress((void**)&wc0, g_wc0);
    cudaGetSymbolAddress((void**)&wr0, g_wr0);
    cudaGetSymbolAddress((void**)&wr1, g_wr1);
    cudaGetSymbolAddress((void**)&wc1, g_wc1);
    cudaGetSymbolAddress((void**)&wo, g_wout);

    const int d3_64 = 262144, d3_32 = 32768, d3_16 = 4096, d3_8 = 512;

    relayoutk<<<d3_64 / 32, 256>>>(x, xv, d3_64);
    {
        const int ntot = 64 * 32 * 8 + 64 * 64 * 8 + 3 * 64 * 64 * 27 + 32 * 64 * 27;
        packall<<<(ntot + 255) / 256, 256>>>(w_h, w_c0, w_r0, w_r1, w_c1, w_out,
                                             wh, wc0, wr0, wr1, wc1, wo);
    }

    const size_t o0 = 0;
    const size_t o1 = o0 + (size_t)32 * d3_64;
    const size_t o2 = o1 + (size_t)32 * d3_32;
    const size_t o3 = o2 + (size_t)32 * d3_16;

    // feas[0] = 0.5*conv_out(x) @64 ; hv <- hx(scaled) voxel-major
    convT<3, 32, EP_OUT><<<2048, 256>>>(xv, wo, out + o0, hv, 64, 64, 27, 1, d3_64);

    // ---- iteration 1: d=32 (256 CTAs per conv) ----
    convT<2, 64, EP_RELU ><<<256, 256>>>(xv, wc0, bY, 0, 32, 64, 8, 1, 0);
    convT<3, 64, EP_RELU ><<<256, 256>>>(bY, wr0, bT, 0, 32, 64, 27, 1, 0);
    convT<3, 64, EP_ADD  ><<<256, 256>>>(bT, wr1, bY, 0, 32, 64, 27, 1, 0);
    convT<3, 64, EP_PLAIN><<<256, 256>>>(bY, wc1, cA, 0, 32, 64, 27, 1, 0);
    convT<2, 64, EP_GATE ><<<256, 256>>>(hv, wh, cA, 0, 32, 32, 8, 1, 0);
    convT<3, 32, EP_OUT  ><<<256, 256>>>(cA, wo, out + o1, hv, 32, 64, 27, 1, d3_32);

    // ---- iteration 2: d=16, tap-split ----
    {
        const int nv = d3_16, NB = nv / 128;
        convT<2, 64, EP_PART><<<dim3(NB, 4), 256>>>(cA, wc0, bP, 0, 16, 64, 8, 4, 0);
        reduceT<EP_RELU><<<(nv * 64 + 255) / 256, 256>>>(bP, bY, 0, nv * 64, nv * 64, 4, 0, 0);
        convT<3, 64, EP_PART><<<dim3(NB, 9), 256>>>(bY, wr0, bP, 0, 16, 64, 27, 9, 0);
        reduceT<EP_RELU><<<(nv * 64 + 255) / 256, 256>>>(bP, bT, 0, nv * 64, nv * 64, 9, 0, 0);
        convT<3, 64, EP_PART><<<dim3(NB, 9), 256>>>(bT, wr1, bP, 0, 16, 64, 27, 9, 0);
        reduceT<EP_ADD><<<(nv * 64 + 255) / 256, 256>>>(bP, bY, 0, nv * 64, nv * 64, 9, 0, 0);
        convT<3, 64, EP_PART><<<dim3(NB, 9), 256>>>(bY, wc1, bP, 0, 16, 64, 27, 9, 0);
        reduceT<EP_PLAIN><<<(nv * 64 + 255) / 256, 256>>>(bP, cB, 0, nv * 64, nv * 64, 9, 0, 0);
        convT<2, 64, EP_PART><<<dim3(NB, 4), 256>>>(hv, wh, bP, 0, 16, 32, 8, 4, 0);
        reduceT<EP_GATE><<<(nv * 64 + 255) / 256, 256>>>(bP, cB, 0, nv * 64, nv * 64, 4, 0, 0);
        convT<3, 32, EP_PART><<<dim3(NB, 9), 256>>>(cB, wo, bP, 0, 16, 64, 27, 9, 0);
        reduceT<EP_OUT><<<(nv * 32 + 255) / 256, 256>>>(bP, out + o2, hv, nv * 32, nv * 32, 9, d3_16, 5);
    }

    // ---- iteration 3: d=8, tap-split ----
    {
        const int nv = d3_8, NB = nv / 128;
        convT<2, 64, EP_PART><<<dim3(NB, 8), 256>>>(cB, wc0, bP, 0, 8, 64, 8, 8, 0);
        reduceT<EP_RELU><<<(nv * 64 + 255) / 256, 256>>>(bP, bY, 0, nv * 64, nv * 64, 8, 0, 0);
        convT<3, 64, EP_PART><<<dim3(NB, 27), 256>>>(bY, wr0, bP, 0, 8, 64, 27, 27, 0);
        reduceT<EP_RELU><<<(nv * 64 + 255) / 256, 256>>>(bP, bT, 0, nv * 64, nv * 64, 27, 0, 0);
        convT<3, 64, EP_PART><<<dim3(NB, 27), 256>>>(bT, wr1, bP, 0, 8, 64, 27, 27, 0);
        reduceT<EP_ADD><<<(nv * 64 + 255) / 256, 256>>>(bP, bY, 0, nv * 64, nv * 64, 27, 0, 0);
        convT<3, 64, EP_PART><<<dim3(NB, 27), 256>>>(bY, wc1, bP, 0, 8, 64, 27, 27, 0);
        reduceT<EP_PLAIN><<<(nv * 64 + 255) / 256, 256>>>(bP, cA, 0, nv * 64, nv * 64, 27, 0, 0);
        convT<2, 64, EP_PART><<<dim3(NB, 8), 256>>>(hv, wh, bP, 0, 8, 32, 8, 8, 0);
        reduceT<EP_GATE><<<(nv * 64 + 255) / 256, 256>>>(bP, cA, 0, nv * 64, nv * 64, 8, 0, 0);
        convT<3, 32, EP_PART><<<dim3(NB, 27), 256>>>(cA, wo, bP, 0, 8, 64, 27, 27, 0);
        reduceT<EP_OUT><<<(nv * 32 + 255) / 256, 256>>>(bP, out + o3, (float*)0, nv * 32, nv * 32, 27, d3_8, 5);
    }
}